// round 14
// baseline (speedup 1.0000x reference)
#include <cuda_runtime.h>
#include <cuda_bf16.h>
#include <cstdint>

// Problem constants
#define BATCH 48
#define CH    64
#define HW    16384      // 128*128
#define KEXP  4
#define HID   16

#define NTILE 128        // pixels per gemm block
#define WS_STRIDE 68     // padded smem stride for W (64 + 4)
#define SMEM_BYTES (64 * WS_STRIDE * 4)   // 17.4 KB (W only)

// Persistent scratch (no allocations allowed)
__device__ float        g_dev[BATCH * CH];           // GAP result
__device__ float        wmix_dev[BATCH * CH * CH];   // mixed weights, tf32-rounded
__device__ unsigned int counter_dev[BATCH];          // zero-initialized; self-resetting

// tf32 destination must be a b32 register in PTX -> "=r"
__device__ __forceinline__ uint32_t to_tf32(float x) {
    uint32_t y;
    asm("cvt.rna.tf32.f32 %0, %1;" : "=r"(y) : "f"(x));
    return y;
}

__device__ __forceinline__ void cp_async16(void* dst_smem, const void* src_gmem) {
    uint32_t d = (uint32_t)__cvta_generic_to_shared(dst_smem);
    asm volatile("cp.async.cg.shared.global [%0], [%1], 16;" :: "r"(d), "l"(src_gmem));
}

__device__ __forceinline__ void store_cs_f2(float* p, float a, float b) {
    asm volatile("st.global.cs.v2.f32 [%0], {%1, %2};" :: "l"(p), "f"(a), "f"(b) : "memory");
}

// ---------------------------------------------------------------------------
// Kernel 1: GAP + (per-batch last-finisher) gating + expert mix.
// One block per (b, ch). The 64th finisher of batch b computes alpha[b] and
// writes the tf32-rounded Wmix[b] (4096 floats, 16/thread), then resets its
// counter for the next graph replay. No consumer waits inside this kernel.
// ---------------------------------------------------------------------------
__global__ __launch_bounds__(256) void meangate_kernel(const float* __restrict__ x,
                                                       const float* __restrict__ experts,
                                                       const float* __restrict__ fc1,
                                                       const float* __restrict__ fc2) {
    const int bc  = blockIdx.x;        // 0..3071
    const int b   = bc >> 6;
    const int tid = threadIdx.x;

    const float4* p = reinterpret_cast<const float4*>(x + (size_t)bc * HW);
    float s = 0.f;
#pragma unroll
    for (int t = 0; t < 16; t++) {
        float4 v = p[tid + t * 256];
        s += (v.x + v.y) + (v.z + v.w);
    }
#pragma unroll
    for (int o = 16; o > 0; o >>= 1) s += __shfl_xor_sync(0xffffffffu, s, o);
    __shared__ float ws[8];
    __shared__ unsigned s_last;
    if ((tid & 31) == 0) ws[tid >> 5] = s;
    __syncthreads();
    if (tid == 0) {
        float t0 = 0.f;
#pragma unroll
        for (int i = 0; i < 8; i++) t0 += ws[i];
        g_dev[bc] = t0 * (1.f / (float)HW);
        __threadfence();                               // release g_dev[bc]
        unsigned old = atomicAdd(&counter_dev[b], 1u);
        s_last = (old == 63u) ? 1u : 0u;
    }
    __syncthreads();
    if (!s_last) return;

    // ---- This block is the last finisher for batch b: gating + Wmix ----
    __threadfence();                                   // acquire g_dev[b*CH..]
    __shared__ float gs[CH];
    __shared__ float hid_s[HID];
    __shared__ float lg_s[KEXP];
    __shared__ float alpha_s[KEXP];

    if (tid < CH) gs[tid] = g_dev[b * CH + tid];
    __syncthreads();
    if (tid < HID) {
        float d = 0.f;
        const float* f1 = fc1 + tid * CH;
#pragma unroll
        for (int c = 0; c < CH; c++) d += f1[c] * gs[c];
        hid_s[tid] = fmaxf(d, 0.f);
    }
    __syncthreads();
    if (tid < KEXP) {
        float d = 0.f;
        const float* f2 = fc2 + tid * HID;
#pragma unroll
        for (int h = 0; h < HID; h++) d += f2[h] * hid_s[h];
        lg_s[tid] = d;
    }
    __syncthreads();
    if (tid == 0) {
        float m = fmaxf(fmaxf(lg_s[0], lg_s[1]), fmaxf(lg_s[2], lg_s[3]));
        float e0 = expf(lg_s[0] - m), e1 = expf(lg_s[1] - m);
        float e2 = expf(lg_s[2] - m), e3 = expf(lg_s[3] - m);
        float inv = 1.f / (e0 + e1 + e2 + e3);
        alpha_s[0] = e0 * inv; alpha_s[1] = e1 * inv;
        alpha_s[2] = e2 * inv; alpha_s[3] = e3 * inv;
        counter_dev[b] = 0;                            // re-arm for next replay
    }
    __syncthreads();

    {
        float a0 = alpha_s[0], a1 = alpha_s[1], a2 = alpha_s[2], a3 = alpha_s[3];
        const float* e0 = experts + 0 * CH * CH;
        const float* e1 = experts + 1 * CH * CH;
        const float* e2 = experts + 2 * CH * CH;
        const float* e3 = experts + 3 * CH * CH;
        float* wout = wmix_dev + (size_t)b * CH * CH;
#pragma unroll
        for (int t = 0; t < 16; t++) {
            int i = tid + t * 256;
            float w = a0 * e0[i] + a1 * e1[i] + a2 * e2[i] + a3 * e3[i];
            wout[i] = __uint_as_float(to_tf32(w));
        }
    }
}

// ---------------------------------------------------------------------------
// Kernel 2: per-batch GEMM  Y[b] (64 x 16384) = Wmix[b] (64x64) @ X[b] (64x16384)
// A fragments: ldmatrix.x4.b16 from smem W tile.
// B fragments: LDG directly from gmem (sector-coalesced; no X smem round-trip).
// 8 warps, warp tile 32x32, smem = W only (17.4 KB).
// ---------------------------------------------------------------------------
__global__ __launch_bounds__(256, 4) void dyconv_kernel(const float* __restrict__ x,
                                                        float* __restrict__ y) {
    extern __shared__ float sm[];
    float* Ws = sm;                       // 64 x WS_STRIDE

    const int b  = (BATCH - 1) - blockIdx.y;   // reversed batch order (L2 reuse)
    const int p0 = blockIdx.x * NTILE;
    const int tid = threadIdx.x;

    const float* wsrc = wmix_dev + (size_t)b * CH * CH;

    // W tile via cp.async: 64 rows x 16 float4, 4 per thread
#pragma unroll
    for (int t = 0; t < 4; t++) {
        int f = tid + t * 256;
        int row = f >> 4, c4 = f & 15;
        cp_async16(Ws + row * WS_STRIDE + c4 * 4, wsrc + row * CH + c4 * 4);
    }
    asm volatile("cp.async.commit_group;" ::: "memory");

    const int lane = tid & 31;
    const int w    = tid >> 5;
    const int wm   = w & 1;       // M half -> M offset 32*wm
    const int wn   = w >> 1;      // N quarter -> N offset 32*wn
    const int r    = lane >> 2;   // 0..7
    const int c    = lane & 3;    // 0..3

    // ldmatrix A-fragment source addresses (per mt)
    uint32_t lm_base[2];
    {
        const int lrow  = lane & 15;
        const int lcol4 = (lane >> 4) * 4;
#pragma unroll
        for (int mt = 0; mt < 2; mt++) {
            int rb = wm * 32 + mt * 16;
            lm_base[mt] = (uint32_t)__cvta_generic_to_shared(
                Ws + (rb + lrow) * WS_STRIDE + lcol4);
        }
    }

    // Per-thread gmem base for B loads: row k = (ks*8 + c), col = p0 + wn*32 + nt*8 + r
    const float* xb = x + ((size_t)b * CH + c) * HW + p0 + wn * 32 + r;

    float acc[2][4][4];
#pragma unroll
    for (int mt = 0; mt < 2; mt++)
#pragma unroll
        for (int nt = 0; nt < 4; nt++)
#pragma unroll
            for (int j = 0; j < 4; j++) acc[mt][nt][j] = 0.f;

    asm volatile("cp.async.wait_group 0;" ::: "memory");
    __syncthreads();

#pragma unroll
    for (int ks = 0; ks < 8; ks++) {
        uint32_t A[2][4];
#pragma unroll
        for (int mt = 0; mt < 2; mt++) {
            asm volatile(
                "ldmatrix.sync.aligned.m8n8.x4.shared.b16 {%0,%1,%2,%3}, [%4];"
                : "=r"(A[mt][0]), "=r"(A[mt][1]), "=r"(A[mt][2]), "=r"(A[mt][3])
                : "r"(lm_base[mt] + (uint32_t)(ks * 32)));
        }
        uint32_t Bf[4][2];
        const float* bp = xb + (ks * 8) * HW;
#pragma unroll
        for (int nt = 0; nt < 4; nt++) {
            Bf[nt][0] = __float_as_uint(bp[nt * 8]);            // k = ks*8+c
            Bf[nt][1] = __float_as_uint(bp[nt * 8 + 4 * HW]);   // k = ks*8+c+4
        }
#pragma unroll
        for (int mt = 0; mt < 2; mt++) {
#pragma unroll
            for (int nt = 0; nt < 4; nt++) {
                asm volatile(
                    "mma.sync.aligned.m16n8k8.row.col.f32.tf32.tf32.f32 "
                    "{%0,%1,%2,%3}, {%4,%5,%6,%7}, {%8,%9}, {%0,%1,%2,%3};\n"
                    : "+f"(acc[mt][nt][0]), "+f"(acc[mt][nt][1]),
                      "+f"(acc[mt][nt][2]), "+f"(acc[mt][nt][3])
                    : "r"(A[mt][0]), "r"(A[mt][1]), "r"(A[mt][2]), "r"(A[mt][3]),
                      "r"(Bf[nt][0]), "r"(Bf[nt][1]));
            }
        }
    }

    // Epilogue: streaming stores (y is never re-read)
    float* ybase = y + ((size_t)b * CH) * HW + p0;
#pragma unroll
    for (int mt = 0; mt < 2; mt++) {
        int o = wm * 32 + mt * 16 + r;
#pragma unroll
        for (int nt = 0; nt < 4; nt++) {
            int col = wn * 32 + nt * 8 + c * 2;
            store_cs_f2(ybase + (size_t)o * HW + col,       acc[mt][nt][0], acc[mt][nt][1]);
            store_cs_f2(ybase + (size_t)(o + 8) * HW + col, acc[mt][nt][2], acc[mt][nt][3]);
        }
    }
}

// ---------------------------------------------------------------------------
extern "C" void kernel_launch(void* const* d_in, const int* in_sizes, int n_in,
                              void* d_out, int out_size) {
    const float* x       = (const float*)d_in[0];  // (48,64,128,128)
    const float* experts = (const float*)d_in[1];  // (4,64,64,1,1)
    const float* fc1     = (const float*)d_in[2];  // (16,64)
    const float* fc2     = (const float*)d_in[3];  // (4,16)
    float* y             = (float*)d_out;          // (48,64,128,128)

    meangate_kernel<<<BATCH * CH, 256>>>(x, experts, fc1, fc2);

    cudaFuncSetAttribute(dyconv_kernel,
                         cudaFuncAttributeMaxDynamicSharedMemorySize, SMEM_BYTES);
    dim3 grid(HW / NTILE, BATCH);
    dyconv_kernel<<<grid, 256, SMEM_BYTES>>>(x, y);
}

// round 15
// speedup vs baseline: 1.2098x; 1.2098x over previous
#include <cuda_runtime.h>
#include <cuda_bf16.h>
#include <cstdint>

// Problem constants
#define BATCH 48
#define CH    64
#define HW    16384      // 128*128
#define KEXP  4
#define HID   16

#define NTILE 128        // pixels per gemm block
#define WS_STRIDE 68     // padded smem stride for W (64 + 4)
#define XS_STRIDE 136    // padded smem stride for X (128 + 8)
#define YS_STRIDE 132    // padded stride for epilogue staging (128 + 4)
#define SMEM_FLOATS (64*WS_STRIDE + 64*XS_STRIDE)
#define SMEM_BYTES  (SMEM_FLOATS * 4)   // 52224 B -> 4 blocks/SM

// Persistent scratch (no allocations allowed)
__device__ float        g_dev[BATCH * CH];           // GAP result
__device__ float        wmix_dev[BATCH * CH * CH];   // mixed weights, tf32-rounded
__device__ unsigned int counter_dev[BATCH];          // zero-init; self-resetting

// tf32 destination must be a b32 register in PTX -> "=r"
__device__ __forceinline__ uint32_t to_tf32(float x) {
    uint32_t y;
    asm("cvt.rna.tf32.f32 %0, %1;" : "=r"(y) : "f"(x));
    return y;
}

__device__ __forceinline__ void cp_async16(void* dst_smem, const void* src_gmem) {
    uint32_t d = (uint32_t)__cvta_generic_to_shared(dst_smem);
    asm volatile("cp.async.cg.shared.global [%0], [%1], 16;" :: "r"(d), "l"(src_gmem));
}

__device__ __forceinline__ void store_cs_f4(float* p, float4 v) {
    asm volatile("st.global.cs.v4.f32 [%0], {%1, %2, %3, %4};"
                 :: "l"(p), "f"(v.x), "f"(v.y), "f"(v.z), "f"(v.w) : "memory");
}

// ---------------------------------------------------------------------------
// Kernel 1: GAP + (per-batch last-finisher) gating + expert mix.
// ---------------------------------------------------------------------------
__global__ __launch_bounds__(256) void meangate_kernel(const float* __restrict__ x,
                                                       const float* __restrict__ experts,
                                                       const float* __restrict__ fc1,
                                                       const float* __restrict__ fc2) {
    const int bc  = blockIdx.x;        // 0..3071
    const int b   = bc >> 6;
    const int tid = threadIdx.x;

    const float4* p = reinterpret_cast<const float4*>(x + (size_t)bc * HW);
    float s = 0.f;
#pragma unroll
    for (int t = 0; t < 16; t++) {
        float4 v = p[tid + t * 256];
        s += (v.x + v.y) + (v.z + v.w);
    }
#pragma unroll
    for (int o = 16; o > 0; o >>= 1) s += __shfl_xor_sync(0xffffffffu, s, o);
    __shared__ float ws[8];
    __shared__ unsigned s_last;
    if ((tid & 31) == 0) ws[tid >> 5] = s;
    __syncthreads();
    if (tid == 0) {
        float t0 = 0.f;
#pragma unroll
        for (int i = 0; i < 8; i++) t0 += ws[i];
        g_dev[bc] = t0 * (1.f / (float)HW);
        __threadfence();                               // release g_dev[bc]
        unsigned old = atomicAdd(&counter_dev[b], 1u);
        s_last = (old == 63u) ? 1u : 0u;
    }
    __syncthreads();
    if (!s_last) return;

    __threadfence();                                   // acquire g_dev[b*CH..]
    __shared__ float gs[CH];
    __shared__ float hid_s[HID];
    __shared__ float lg_s[KEXP];
    __shared__ float alpha_s[KEXP];

    if (tid < CH) gs[tid] = g_dev[b * CH + tid];
    __syncthreads();
    if (tid < HID) {
        float d = 0.f;
        const float* f1 = fc1 + tid * CH;
#pragma unroll
        for (int c = 0; c < CH; c++) d += f1[c] * gs[c];
        hid_s[tid] = fmaxf(d, 0.f);
    }
    __syncthreads();
    if (tid < KEXP) {
        float d = 0.f;
        const float* f2 = fc2 + tid * HID;
#pragma unroll
        for (int h = 0; h < HID; h++) d += f2[h] * hid_s[h];
        lg_s[tid] = d;
    }
    __syncthreads();
    if (tid == 0) {
        float m = fmaxf(fmaxf(lg_s[0], lg_s[1]), fmaxf(lg_s[2], lg_s[3]));
        float e0 = expf(lg_s[0] - m), e1 = expf(lg_s[1] - m);
        float e2 = expf(lg_s[2] - m), e3 = expf(lg_s[3] - m);
        float inv = 1.f / (e0 + e1 + e2 + e3);
        alpha_s[0] = e0 * inv; alpha_s[1] = e1 * inv;
        alpha_s[2] = e2 * inv; alpha_s[3] = e3 * inv;
        counter_dev[b] = 0;                            // re-arm for next replay
    }
    __syncthreads();

    {
        float a0 = alpha_s[0], a1 = alpha_s[1], a2 = alpha_s[2], a3 = alpha_s[3];
        const float* e0 = experts + 0 * CH * CH;
        const float* e1 = experts + 1 * CH * CH;
        const float* e2 = experts + 2 * CH * CH;
        const float* e3 = experts + 3 * CH * CH;
        float* wout = wmix_dev + (size_t)b * CH * CH;
#pragma unroll
        for (int t = 0; t < 16; t++) {
            int i = tid + t * 256;
            float w = a0 * e0[i] + a1 * e1[i] + a2 * e2[i] + a3 * e3[i];
            wout[i] = __uint_as_float(to_tf32(w));
        }
    }
}

// ---------------------------------------------------------------------------
// Kernel 2: per-batch GEMM, L1-optimized epilogue.
// Mainloop: split-K cp.async X tile, ldmatrix-A, raw-bits B (R13-proven).
// Epilogue: acc -> smem staging (reusing X region) -> coalesced st.cs.v4.
// 8 warps, warp tile 32x32, 4 blocks/SM.
// ---------------------------------------------------------------------------
__global__ __launch_bounds__(256, 4) void dyconv_kernel(const float* __restrict__ x,
                                                        float* __restrict__ y) {
    extern __shared__ float sm[];
    float* Ws = sm;                       // 64 x WS_STRIDE
    float* Xs = sm + 64 * WS_STRIDE;      // 64 x XS_STRIDE (mainloop) / staging (epilogue)

    const int b  = (BATCH - 1) - blockIdx.y;   // reversed batch order (L2 reuse)
    const int p0 = blockIdx.x * NTILE;
    const int tid = threadIdx.x;

    const float* wsrc = wmix_dev + (size_t)b * CH * CH;
    const float* xsrc = x + ((size_t)b * CH) * HW + p0;

    // Group 0: X rows 0..31 (k-half 0) + W tile
#pragma unroll
    for (int t = 0; t < 4; t++) {
        int f = tid + t * 256;
        int i = f >> 5, p4 = f & 31;      // i in 0..31
        cp_async16(Xs + i * XS_STRIDE + p4 * 4, xsrc + (size_t)i * HW + p4 * 4);
    }
#pragma unroll
    for (int t = 0; t < 4; t++) {
        int f = tid + t * 256;
        int row = f >> 4, c4 = f & 15;
        cp_async16(Ws + row * WS_STRIDE + c4 * 4, wsrc + row * CH + c4 * 4);
    }
    asm volatile("cp.async.commit_group;" ::: "memory");

    // Group 1: X rows 32..63 (k-half 1)
#pragma unroll
    for (int t = 4; t < 8; t++) {
        int f = tid + t * 256;
        int i = f >> 5, p4 = f & 31;      // i in 32..63
        cp_async16(Xs + i * XS_STRIDE + p4 * 4, xsrc + (size_t)i * HW + p4 * 4);
    }
    asm volatile("cp.async.commit_group;" ::: "memory");

    const int lane = tid & 31;
    const int w    = tid >> 5;
    const int wm   = w & 1;       // M half -> M offset 32*wm
    const int wn   = w >> 1;      // N quarter -> N offset 32*wn
    const int r    = lane >> 2;   // 0..7
    const int c    = lane & 3;    // 0..3

    // ldmatrix A-fragment source addresses (per mt)
    uint32_t lm_base[2];
    {
        const int lrow  = lane & 15;
        const int lcol4 = (lane >> 4) * 4;
#pragma unroll
        for (int mt = 0; mt < 2; mt++) {
            int rb = wm * 32 + mt * 16;
            lm_base[mt] = (uint32_t)__cvta_generic_to_shared(
                Ws + (rb + lrow) * WS_STRIDE + lcol4);
        }
    }

    float acc[2][4][4];
#pragma unroll
    for (int mt = 0; mt < 2; mt++)
#pragma unroll
        for (int nt = 0; nt < 4; nt++)
#pragma unroll
            for (int j = 0; j < 4; j++) acc[mt][nt][j] = 0.f;

    // Wait for group0 (k-half 0 + W); group1 still in flight.
    asm volatile("cp.async.wait_group 1;" ::: "memory");
    __syncthreads();

#pragma unroll
    for (int half = 0; half < 2; half++) {
        if (half == 1) {
            asm volatile("cp.async.wait_group 0;" ::: "memory");
            __syncthreads();
        }
#pragma unroll
        for (int kss = 0; kss < 4; kss++) {
            const int ks = half * 4 + kss;
            uint32_t A[2][4];
#pragma unroll
            for (int mt = 0; mt < 2; mt++) {
                asm volatile(
                    "ldmatrix.sync.aligned.m8n8.x4.shared.b16 {%0,%1,%2,%3}, [%4];"
                    : "=r"(A[mt][0]), "=r"(A[mt][1]), "=r"(A[mt][2]), "=r"(A[mt][3])
                    : "r"(lm_base[mt] + (uint32_t)(ks * 32)));
            }
            uint32_t Bf[4][2];
#pragma unroll
            for (int nt = 0; nt < 4; nt++) {
                const float* base = Xs + (ks * 8 + c) * XS_STRIDE + wn * 32 + nt * 8 + r;
                Bf[nt][0] = __float_as_uint(base[0]);                 // raw fp32 -> tf32 (RZ)
                Bf[nt][1] = __float_as_uint(base[4 * XS_STRIDE]);
            }
#pragma unroll
            for (int mt = 0; mt < 2; mt++) {
#pragma unroll
                for (int nt = 0; nt < 4; nt++) {
                    asm volatile(
                        "mma.sync.aligned.m16n8k8.row.col.f32.tf32.tf32.f32 "
                        "{%0,%1,%2,%3}, {%4,%5,%6,%7}, {%8,%9}, {%0,%1,%2,%3};\n"
                        : "+f"(acc[mt][nt][0]), "+f"(acc[mt][nt][1]),
                          "+f"(acc[mt][nt][2]), "+f"(acc[mt][nt][3])
                        : "r"(A[mt][0]), "r"(A[mt][1]), "r"(A[mt][2]), "r"(A[mt][3]),
                          "r"(Bf[nt][0]), "r"(Bf[nt][1]));
                }
            }
        }
    }

    // ---- Epilogue: stage through smem (X region is dead), then coalesced v4 ----
    __syncthreads();                       // all X reads done before overwrite
    float* Ys = Xs;                        // 64 rows x YS_STRIDE
#pragma unroll
    for (int mt = 0; mt < 2; mt++) {
        int o = wm * 32 + mt * 16 + r;
#pragma unroll
        for (int nt = 0; nt < 4; nt++) {
            int col = wn * 32 + nt * 8 + c * 2;
            *reinterpret_cast<float2*>(Ys + o * YS_STRIDE + col) =
                make_float2(acc[mt][nt][0], acc[mt][nt][1]);
            *reinterpret_cast<float2*>(Ys + (o + 8) * YS_STRIDE + col) =
                make_float2(acc[mt][nt][2], acc[mt][nt][3]);
        }
    }
    __syncthreads();

    float* ybase = y + ((size_t)b * CH) * HW + p0;
#pragma unroll
    for (int i = 0; i < 8; i++) {
        int o = w * 8 + i;                 // warp w owns rows w*8 .. w*8+7
        float4 v = *reinterpret_cast<float4*>(Ys + o * YS_STRIDE + lane * 4);
        store_cs_f4(ybase + (size_t)o * HW + lane * 4, v);
    }
}

// ---------------------------------------------------------------------------
extern "C" void kernel_launch(void* const* d_in, const int* in_sizes, int n_in,
                              void* d_out, int out_size) {
    const float* x       = (const float*)d_in[0];  // (48,64,128,128)
    const float* experts = (const float*)d_in[1];  // (4,64,64,1,1)
    const float* fc1     = (const float*)d_in[2];  // (16,64)
    const float* fc2     = (const float*)d_in[3];  // (4,16)
    float* y             = (float*)d_out;          // (48,64,128,128)

    meangate_kernel<<<BATCH * CH, 256>>>(x, experts, fc1, fc2);

    cudaFuncSetAttribute(dyconv_kernel,
                         cudaFuncAttributeMaxDynamicSharedMemorySize, SMEM_BYTES);
    dim3 grid(HW / NTILE, BATCH);
    dyconv_kernel<<<grid, 256, SMEM_BYTES>>>(x, y);
}